// round 2
// baseline (speedup 1.0000x reference)
#include <cuda_runtime.h>

// WaveletBlock fused kernel: DWT -> GEMM1(+bias,SiLU) -> GEMM2(+bias) -> IDWT
// Shapes: x (16, 64, 128, 128) fp32; conv_w (256,256); conv_out_w (256,256)
// Each CTA: one (image n, half-row hh) => 64 spatial positions, full 256-ch GEMMs.

#define NIMG 16
#define CCH  64
#define HH_  128
#define WW_  128
#define KDIM 256
#define AS   68           // padded row stride for A smem (floats)
#define SMEM_BYTES ((256*AS + 16*256) * 4)

__device__ __forceinline__ void gemm_k256(const float* __restrict__ Wg,
                                          float* __restrict__ A,
                                          float* __restrict__ Wp,
                                          int tid, int tx, int m0,
                                          float acc[8][8])
{
    for (int kp = 0; kp < 16; ++kp) {
        __syncthreads();
        // Load 16-wide k-panel: thread t loads row n=t, cols kp*16..kp*16+15
        const float4* wrow = (const float4*)(Wg + (size_t)tid * 256 + kp * 16);
        #pragma unroll
        for (int q = 0; q < 4; ++q) {
            float4 v = wrow[q];
            Wp[(q * 4 + 0) * 256 + tid] = v.x;
            Wp[(q * 4 + 1) * 256 + tid] = v.y;
            Wp[(q * 4 + 2) * 256 + tid] = v.z;
            Wp[(q * 4 + 3) * 256 + tid] = v.w;
        }
        __syncthreads();
        #pragma unroll
        for (int kk = 0; kk < 16; ++kk) {
            int k = kp * 16 + kk;
            float4 a0 = *(const float4*)&A[k * AS + m0];
            float4 a1 = *(const float4*)&A[k * AS + m0 + 4];
            float av[8] = {a0.x, a0.y, a0.z, a0.w, a1.x, a1.y, a1.z, a1.w};
            float bv[8];
            #pragma unroll
            for (int j = 0; j < 8; ++j) bv[j] = Wp[kk * 256 + tx + 32 * j];
            #pragma unroll
            for (int i = 0; i < 8; ++i)
                #pragma unroll
                for (int j = 0; j < 8; ++j)
                    acc[i][j] += av[i] * bv[j];
        }
    }
}

extern "C" __global__ void __launch_bounds__(256, 2)
wavelet_fused(const float* __restrict__ x,
              const float* __restrict__ conv_w,
              const float* __restrict__ conv_b,
              const float* __restrict__ conv_out_w,
              const float* __restrict__ conv_out_b,
              float* __restrict__ out)
{
    extern __shared__ float smem[];
    float* A  = smem;              // [256][AS]  k-major activation tile
    float* Wp = smem + 256 * AS;   // [16][256]  weight k-panel

    const int tid   = threadIdx.x;
    const int blk   = blockIdx.x;        // 0..1023
    const int n_img = blk >> 6;
    const int hh    = blk & 63;

    const size_t img_off = (size_t)n_img * CCH * HH_ * WW_;
    const int row0 = (2 * hh) * WW_;

    // ---- DWT: load 2 rows x 64 channels, butterfly into A[k][m] ----
    #pragma unroll
    for (int it = 0; it < 16; ++it) {
        int idx = it * 256 + tid;
        int c  = idx >> 6;
        int wh = idx & 63;
        const float* p = x + img_off + (size_t)c * (HH_ * WW_) + row0 + 2 * wh;
        float2 top = *(const float2*)p;           // row 2hh:  (x1, x3)
        float2 bot = *(const float2*)(p + WW_);   // row 2hh+1:(x2, x4)
        float x1 = top.x * 0.5f, x3 = top.y * 0.5f;
        float x2 = bot.x * 0.5f, x4 = bot.y * 0.5f;
        A[(c      ) * AS + wh] =  x1 + x2 + x3 + x4;
        A[(c +  64) * AS + wh] = -x1 - x2 + x3 + x4;
        A[(c + 128) * AS + wh] = -x1 + x2 - x3 + x4;
        A[(c + 192) * AS + wh] =  x1 - x2 - x3 + x4;
    }

    const int ty = tid >> 5;     // 0..7
    const int tx = tid & 31;     // 0..31
    const int m0 = ty * 8;       // 8 positions per thread

    float acc[8][8];

    // ---- GEMM1: feat = dwt @ conv_w^T ----
    #pragma unroll
    for (int i = 0; i < 8; ++i)
        #pragma unroll
        for (int j = 0; j < 8; ++j) acc[i][j] = 0.f;
    gemm_k256(conv_w, A, Wp, tid, tx, m0, acc);
    __syncthreads();   // everyone done reading A

    // bias + SiLU, write feat back into A (layout [h][m])
    #pragma unroll
    for (int j = 0; j < 8; ++j) {
        int n = tx + 32 * j;
        float b = __ldg(&conv_b[n]);
        #pragma unroll
        for (int i = 0; i < 8; ++i) {
            float v = acc[i][j] + b;
            v = v * (1.f / (1.f + __expf(-v)));
            A[n * AS + m0 + i] = v;
        }
    }
    // (gemm_k256's leading __syncthreads orders these writes before reads)

    // ---- GEMM2: y = feat @ conv_out_w^T ----
    #pragma unroll
    for (int i = 0; i < 8; ++i)
        #pragma unroll
        for (int j = 0; j < 8; ++j) acc[i][j] = 0.f;
    gemm_k256(conv_out_w, A, Wp, tid, tx, m0, acc);
    __syncthreads();   // everyone done reading feat

    // bias, write y into A (layout [o][m])
    #pragma unroll
    for (int j = 0; j < 8; ++j) {
        int n = tx + 32 * j;
        float b = __ldg(&conv_out_b[n]);
        #pragma unroll
        for (int i = 0; i < 8; ++i)
            A[n * AS + m0 + i] = acc[i][j] + b;
    }
    __syncthreads();

    // ---- IDWT + store ----
    #pragma unroll
    for (int it = 0; it < 16; ++it) {
        int idx = it * 256 + tid;
        int co = idx >> 6;
        int wh = idx & 63;
        float y1 = A[(co      ) * AS + wh] * 0.5f;
        float y2 = A[(co +  64) * AS + wh] * 0.5f;
        float y3 = A[(co + 128) * AS + wh] * 0.5f;
        float y4 = A[(co + 192) * AS + wh] * 0.5f;
        float va = y1 - y2 - y3 + y4;   // (2hh,   2wh)
        float vb = y1 - y2 + y3 - y4;   // (2hh+1, 2wh)
        float vc = y1 + y2 - y3 - y4;   // (2hh,   2wh+1)
        float vd = y1 + y2 + y3 + y4;   // (2hh+1, 2wh+1)
        float* p = out + img_off + (size_t)co * (HH_ * WW_) + row0 + 2 * wh;
        *(float2*)p          = make_float2(va, vc);
        *(float2*)(p + WW_)  = make_float2(vb, vd);
    }
}

extern "C" void kernel_launch(void* const* d_in, const int* in_sizes, int n_in,
                              void* d_out, int out_size)
{
    const float* x          = (const float*)d_in[0];
    const float* conv_w     = (const float*)d_in[1];
    const float* conv_b     = (const float*)d_in[2];
    const float* conv_out_w = (const float*)d_in[3];
    const float* conv_out_b = (const float*)d_in[4];
    float* out = (float*)d_out;

    cudaFuncSetAttribute(wavelet_fused,
                         cudaFuncAttributeMaxDynamicSharedMemorySize, SMEM_BYTES);
    wavelet_fused<<<1024, 256, SMEM_BYTES>>>(x, conv_w, conv_b,
                                             conv_out_w, conv_out_b, out);
}

// round 5
// speedup vs baseline: 2.2007x; 2.2007x over previous
#include <cuda_runtime.h>
#include <cuda_bf16.h>
#include <cstdint>

// WaveletBlock fused: DWT -> GEMM1(+bias,SiLU) -> GEMM2(+bias) -> IDWT
// GEMMs on warp-level mma.sync bf16 (3-pass hi/lo split for fp32 accuracy).
// Per CTA: M_tile=128 (one image, hh-pair), N=K=256. 512 CTAs, 256 threads.

#define C_   64
#define H_   128
#define W_   128
#define HW_  (H_*W_)

#define ARS  528          // A smem row stride (bytes), 256 bf16 + 16B pad
#define WRS  80           // W panel row stride (bytes), 32 bf16 + 16B pad
#define SM_A_HI  0
#define SM_A_LO  67584    // 128*528
#define SM_W     135168
#define WBUF     40960    // one panel buffer: hi 256*80 + lo 256*80
#define WHALF    20480
#define SM_TOTAL 217088   // 135168 + 2*40960

__device__ __nv_bfloat16 g_Whi[2][256 * 256];
__device__ __nv_bfloat16 g_Wlo[2][256 * 256];

// ---------------- prep: split weights fp32 -> bf16 hi/lo ----------------
__global__ void prep_split(const float* __restrict__ w0, const float* __restrict__ w1)
{
    int i = blockIdx.x * blockDim.x + threadIdx.x;   // 0..65535
    float a0 = w0[i];
    __nv_bfloat16 h0 = __float2bfloat16(a0);
    g_Whi[0][i] = h0;
    g_Wlo[0][i] = __float2bfloat16(a0 - __bfloat162float(h0));
    float a1 = w1[i];
    __nv_bfloat16 h1 = __float2bfloat16(a1);
    g_Whi[1][i] = h1;
    g_Wlo[1][i] = __float2bfloat16(a1 - __bfloat162float(h1));
}

// ---------------- helpers ----------------
__device__ __forceinline__ uint32_t smem_u32(const void* p) {
    uint32_t a;
    asm("{ .reg .u64 t; cvta.to.shared.u64 t, %1; cvt.u32.u64 %0, t; }" : "=r"(a) : "l"(p));
    return a;
}
#define LDX4(r, a) \
    asm volatile("ldmatrix.sync.aligned.m8n8.x4.shared.b16 {%0,%1,%2,%3}, [%4];" \
        : "=r"((r)[0]), "=r"((r)[1]), "=r"((r)[2]), "=r"((r)[3]) : "r"(a))
#define MMA(c, a, b0, b1) \
    asm volatile("mma.sync.aligned.m16n8k16.row.col.f32.bf16.bf16.f32 " \
        "{%0,%1,%2,%3},{%4,%5,%6,%7},{%8,%9},{%0,%1,%2,%3};" \
        : "+f"((c)[0]), "+f"((c)[1]), "+f"((c)[2]), "+f"((c)[3]) \
        : "r"((a)[0]), "r"((a)[1]), "r"((a)[2]), "r"((a)[3]), "r"(b0), "r"(b1))
#define CP_COMMIT() asm volatile("cp.async.commit_group;" ::: "memory")
#define CP_WAIT0()  asm volatile("cp.async.wait_group 0;" ::: "memory")
#define CP_WAIT1()  asm volatile("cp.async.wait_group 1;" ::: "memory")

__device__ __forceinline__ uint32_t pack_bf2(float a, float b) {
    __nv_bfloat162 h = __floats2bfloat162_rn(a, b);
    return *reinterpret_cast<uint32_t*>(&h);
}
__device__ __forceinline__ void split_pair(float a, float b, uint32_t& hi, uint32_t& lo) {
    __nv_bfloat16 ha = __float2bfloat16(a), hb = __float2bfloat16(b);
    float ra = a - __bfloat162float(ha), rb = b - __bfloat162float(hb);
    hi = pack_bf2(__bfloat162float(ha), __bfloat162float(hb));
    lo = pack_bf2(ra, rb);
}
__device__ __forceinline__ float silu(float v) {
    return v * (1.0f / (1.0f + __expf(-v)));
}

// copy one W k-panel (kp: k = kp*32..+32) hi+lo into smem buffer via cp.async
__device__ __forceinline__ void copy_panel(uint32_t dstbase,
                                           const __nv_bfloat16* __restrict__ Whi,
                                           const __nv_bfloat16* __restrict__ Wlo,
                                           int kp, int tid)
{
    #pragma unroll
    for (int i = 0; i < 8; ++i) {
        int id = i * 256 + tid;            // 0..2047
        int half = id >> 10;               // 0=hi 1=lo
        int rem  = id & 1023;
        int n = rem >> 2, c = rem & 3;     // row, 16B chunk
        const __nv_bfloat16* src = (half ? Wlo : Whi) + n * 256 + kp * 32 + c * 8;
        uint32_t dst = dstbase + half * WHALF + n * WRS + c * 16;
        asm volatile("cp.async.cg.shared.global [%0], [%1], 16;" :: "r"(dst), "l"(src) : "memory");
    }
}

// One GEMM mainloop: acc += A(128x256, smem hi/lo) * W^T (256x256, global hi/lo)
// Panel 0 must already be issued+committed into buffer 0 by the caller.
__device__ __forceinline__ void gemm_main(uint32_t sb,
                                          const __nv_bfloat16* __restrict__ Whi,
                                          const __nv_bfloat16* __restrict__ Wlo,
                                          float acc[4][8][4],
                                          int tid, int l, int mw, int nw)
{
    // per-lane ldmatrix address bases
    const uint32_t aHiBase = sb + SM_A_HI
        + (uint32_t)(mw * 64 + ((l >> 3) & 1) * 8 + (l & 7)) * ARS
        + ((l >> 4) & 1) * 16;
    const uint32_t aLoBase = aHiBase + (SM_A_LO - SM_A_HI);
    // B: non-trans ldmatrix, rows are W's n-rows.
    // matrices: m0=(n+0,k+0) m1=(n+0,k+8) m2=(n+8,k+0) m3=(n+8,k+8)
    const uint32_t bOff =
        (uint32_t)(nw * 16 + ((l >> 4) & 1) * 8 + (l & 7)) * WRS
        + ((l >> 3) & 1) * 16;

    #pragma unroll 1
    for (int p = 0; p < 8; ++p) {
        if (p < 7) {
            copy_panel(sb + SM_W + ((p + 1) & 1) * WBUF, Whi, Wlo, p + 1, tid);
            CP_COMMIT();
            CP_WAIT1();
        } else {
            CP_WAIT0();
        }
        __syncthreads();
        const uint32_t wb = sb + SM_W + (p & 1) * WBUF;

        #pragma unroll
        for (int ks = 0; ks < 2; ++ks) {
            const int kg = p * 2 + ks;
            uint32_t Bh[4][4], Bl[4][4], Ah[4][4];
            #pragma unroll
            for (int q = 0; q < 4; ++q) {
                uint32_t ba = wb + bOff + (uint32_t)q * (64 * WRS) + ks * 32;
                LDX4(Bh[q], ba);
                LDX4(Bl[q], ba + WHALF);
            }
            #pragma unroll
            for (int i = 0; i < 4; ++i)
                LDX4(Ah[i], aHiBase + (uint32_t)i * (16 * ARS) + kg * 32);
            // pass 1: hi*hi
            #pragma unroll
            for (int i = 0; i < 4; ++i)
                #pragma unroll
                for (int q = 0; q < 4; ++q) {
                    MMA(acc[i][2 * q],     Ah[i], Bh[q][0], Bh[q][1]);
                    MMA(acc[i][2 * q + 1], Ah[i], Bh[q][2], Bh[q][3]);
                }
            // pass 2: hi*lo(W)
            #pragma unroll
            for (int i = 0; i < 4; ++i)
                #pragma unroll
                for (int q = 0; q < 4; ++q) {
                    MMA(acc[i][2 * q],     Ah[i], Bl[q][0], Bl[q][1]);
                    MMA(acc[i][2 * q + 1], Ah[i], Bl[q][2], Bl[q][3]);
                }
            // pass 3: lo(A)*hi
            #pragma unroll
            for (int i = 0; i < 4; ++i)
                LDX4(Ah[i], aLoBase + (uint32_t)i * (16 * ARS) + kg * 32);
            #pragma unroll
            for (int i = 0; i < 4; ++i)
                #pragma unroll
                for (int q = 0; q < 4; ++q) {
                    MMA(acc[i][2 * q],     Ah[i], Bh[q][0], Bh[q][1]);
                    MMA(acc[i][2 * q + 1], Ah[i], Bh[q][2], Bh[q][3]);
                }
        }
        __syncthreads();
    }
}

extern "C" __global__ void __launch_bounds__(256, 1)
wavelet_mma(const float* __restrict__ x,
            const float* __restrict__ conv_b,
            const float* __restrict__ conv_out_b,
            float* __restrict__ out)
{
    extern __shared__ char sm[];
    const uint32_t sb = smem_u32(sm);
    const int tid = threadIdx.x;
    const int l  = tid & 31, wid = tid >> 5;
    const int nw = wid & 3,  mw  = wid >> 2;
    const int blk = blockIdx.x;
    const int n_img = blk >> 5, p = blk & 31;
    const size_t img_off = (size_t)n_img * C_ * HW_;
    const float* xb = x + img_off + (size_t)(4 * p) * W_;

    // prefetch GEMM1 panel 0 while we do the DWT
    copy_panel(sb + SM_W, g_Whi[0], g_Wlo[0], 0, tid);
    CP_COMMIT();

    // ---- DWT -> A hi/lo [m=128][k=256] bf16, padded rows ----
    #pragma unroll
    for (int i = 0; i < 16; ++i) {
        int e = i * 256 + tid;
        int cpair = e >> 7, m = e & 127;
        int c0 = cpair * 2, hl = m >> 6, wh = m & 63;
        const float* px = xb + (size_t)c0 * HW_ + (size_t)(2 * hl) * W_ + 2 * wh;
        float2 t0 = *(const float2*)px,         b0 = *(const float2*)(px + W_);
        float2 t1 = *(const float2*)(px + HW_), b1 = *(const float2*)(px + HW_ + W_);
        float x1 = t0.x * 0.5f, x3 = t0.y * 0.5f, x2 = b0.x * 0.5f, x4 = b0.y * 0.5f;
        float qa[4] = { x1 + x2 + x3 + x4, -x1 - x2 + x3 + x4,
                       -x1 + x2 - x3 + x4,  x1 - x2 - x3 + x4};
        x1 = t1.x * 0.5f; x3 = t1.y * 0.5f; x2 = b1.x * 0.5f; x4 = b1.y * 0.5f;
        float qb[4] = { x1 + x2 + x3 + x4, -x1 - x2 + x3 + x4,
                       -x1 + x2 - x3 + x4,  x1 - x2 - x3 + x4};
        #pragma unroll
        for (int q = 0; q < 4; ++q) {
            uint32_t hi, lo;
            split_pair(qa[q], qb[q], hi, lo);
            uint32_t off = (uint32_t)m * ARS + (uint32_t)(q * 64 + c0) * 2;
            *(uint32_t*)(sm + SM_A_HI + off) = hi;
            *(uint32_t*)(sm + SM_A_LO + off) = lo;
        }
    }

    float acc[4][8][4];
    #pragma unroll
    for (int i = 0; i < 4; ++i)
        #pragma unroll
        for (int j = 0; j < 8; ++j)
            #pragma unroll
            for (int r = 0; r < 4; ++r) acc[i][j][r] = 0.f;

    // ---- GEMM1 ----
    gemm_main(sb, g_Whi[0], g_Wlo[0], acc, tid, l, mw, nw);

    // prefetch GEMM2 panel 0 (W buf0 free: last read at p=6)
    copy_panel(sb + SM_W, g_Whi[1], g_Wlo[1], 0, tid);
    CP_COMMIT();

    // ---- epilogue 1: bias + SiLU -> A hi/lo (feat) ----
    {
        float bv[4][2][2];
        #pragma unroll
        for (int q = 0; q < 4; ++q)
            #pragma unroll
            for (int s = 0; s < 2; ++s)
                #pragma unroll
                for (int cp = 0; cp < 2; ++cp)
                    bv[q][s][cp] = __ldg(conv_b + q * 64 + nw * 16 + s * 8 + (l & 3) * 2 + cp);
        #pragma unroll
        for (int i = 0; i < 4; ++i)
            #pragma unroll
            for (int rh = 0; rh < 2; ++rh) {
                int m = mw * 64 + i * 16 + rh * 8 + (l >> 2);
                #pragma unroll
                for (int q = 0; q < 4; ++q)
                    #pragma unroll
                    for (int s = 0; s < 2; ++s) {
                        float v0 = silu(acc[i][2 * q + s][rh * 2 + 0] + bv[q][s][0]);
                        float v1 = silu(acc[i][2 * q + s][rh * 2 + 1] + bv[q][s][1]);
                        uint32_t hi, lo;
                        split_pair(v0, v1, hi, lo);
                        int col = q * 64 + nw * 16 + s * 8 + (l & 3) * 2;
                        uint32_t off = (uint32_t)m * ARS + (uint32_t)col * 2;
                        *(uint32_t*)(sm + SM_A_HI + off) = hi;
                        *(uint32_t*)(sm + SM_A_LO + off) = lo;
                    }
            }
    }
    #pragma unroll
    for (int i = 0; i < 4; ++i)
        #pragma unroll
        for (int j = 0; j < 8; ++j)
            #pragma unroll
            for (int r = 0; r < 4; ++r) acc[i][j][r] = 0.f;

    // ---- GEMM2 ---- (gemm_main's first __syncthreads orders epilogue writes)
    gemm_main(sb, g_Whi[1], g_Wlo[1], acc, tid, l, mw, nw);

    // ---- epilogue 2: bias + IDWT + store ----
    {
        float bv[4][2][2];
        #pragma unroll
        for (int q = 0; q < 4; ++q)
            #pragma unroll
            for (int s = 0; s < 2; ++s)
                #pragma unroll
                for (int cp = 0; cp < 2; ++cp)
                    bv[q][s][cp] = __ldg(conv_out_b + q * 64 + nw * 16 + s * 8 + (l & 3) * 2 + cp);
        const int r0 = 4 * p + 2 * mw;     // hl == mw
        #pragma unroll
        for (int i = 0; i < 4; ++i)
            #pragma unroll
            for (int rh = 0; rh < 2; ++rh) {
                int m = mw * 64 + i * 16 + rh * 8 + (l >> 2);
                int wh = m & 63;
                #pragma unroll
                for (int s = 0; s < 2; ++s)
                    #pragma unroll
                    for (int cp = 0; cp < 2; ++cp) {
                        int co = nw * 16 + s * 8 + (l & 3) * 2 + cp;
                        float y1 = (acc[i][0 + s][rh * 2 + cp] + bv[0][s][cp]) * 0.5f;
                        float y2 = (acc[i][2 + s][rh * 2 + cp] + bv[1][s][cp]) * 0.5f;
                        float y3 = (acc[i][4 + s][rh * 2 + cp] + bv[2][s][cp]) * 0.5f;
                        float y4 = (acc[i][6 + s][rh * 2 + cp] + bv[3][s][cp]) * 0.5f;
                        float va = y1 - y2 - y3 + y4;
                        float vb = y1 - y2 + y3 - y4;
                        float vc = y1 + y2 - y3 - y4;
                        float vd = y1 + y2 + y3 + y4;
                        float* po = out + img_off + (size_t)co * HW_
                                  + (size_t)r0 * W_ + 2 * wh;
                        *(float2*)po        = make_float2(va, vc);
                        *(float2*)(po + W_) = make_float2(vb, vd);
                    }
            }
    }
}

extern "C" void kernel_launch(void* const* d_in, const int* in_sizes, int n_in,
                              void* d_out, int out_size)
{
    const float* x          = (const float*)d_in[0];
    const float* conv_w     = (const float*)d_in[1];
    const float* conv_b     = (const float*)d_in[2];
    const float* conv_out_w = (const float*)d_in[3];
    const float* conv_out_b = (const float*)d_in[4];
    float* out = (float*)d_out;

    prep_split<<<256, 256>>>(conv_w, conv_out_w);

    cudaFuncSetAttribute(wavelet_mma,
                         cudaFuncAttributeMaxDynamicSharedMemorySize, SM_TOTAL);
    wavelet_mma<<<512, 256, SM_TOTAL>>>(x, conv_b, conv_out_b, out);
}

// round 6
// speedup vs baseline: 2.3782x; 1.0806x over previous
#include <cuda_runtime.h>
#include <cuda_bf16.h>
#include <cstdint>

// WaveletBlock fused: DWT -> GEMM1(+bias,SiLU) -> GEMM2(+bias) -> IDWT
// bf16 mma.sync, 3-pass hi/lo split. 512 CTAs x 512 threads (16 warps).
// Warp grid 2m x 8n; each n-warp owns 8 channels across all 4 quadrants.

#define C_   64
#define H_   128
#define W_   128
#define HW_  (H_*W_)

#define ARS  528          // A smem row stride (bytes), 256 bf16 + 16B pad
#define WRS  80           // W panel row stride (bytes), 32 bf16 + 16B pad
#define SM_A_HI  0
#define SM_A_LO  67584    // 128*528
#define SM_W     135168
#define WBUF     40960    // one panel buffer: hi 256*80 + lo 256*80
#define WHALF    20480
#define SM_TOTAL 217088   // 135168 + 2*40960

__device__ __nv_bfloat16 g_Whi[2][256 * 256];
__device__ __nv_bfloat16 g_Wlo[2][256 * 256];

// ---------------- prep: split weights fp32 -> bf16 hi/lo ----------------
__global__ void prep_split(const float* __restrict__ w0, const float* __restrict__ w1)
{
    int i = blockIdx.x * blockDim.x + threadIdx.x;
    float a0 = w0[i];
    __nv_bfloat16 h0 = __float2bfloat16(a0);
    g_Whi[0][i] = h0;
    g_Wlo[0][i] = __float2bfloat16(a0 - __bfloat162float(h0));
    float a1 = w1[i];
    __nv_bfloat16 h1 = __float2bfloat16(a1);
    g_Whi[1][i] = h1;
    g_Wlo[1][i] = __float2bfloat16(a1 - __bfloat162float(h1));
}

// ---------------- helpers ----------------
__device__ __forceinline__ uint32_t smem_u32(const void* p) {
    uint32_t a;
    asm("{ .reg .u64 t; cvta.to.shared.u64 t, %1; cvt.u32.u64 %0, t; }" : "=r"(a) : "l"(p));
    return a;
}
#define LDX4(r, a) \
    asm volatile("ldmatrix.sync.aligned.m8n8.x4.shared.b16 {%0,%1,%2,%3}, [%4];" \
        : "=r"((r)[0]), "=r"((r)[1]), "=r"((r)[2]), "=r"((r)[3]) : "r"(a))
#define LDX2(r, a) \
    asm volatile("ldmatrix.sync.aligned.m8n8.x2.shared.b16 {%0,%1}, [%2];" \
        : "=r"((r)[0]), "=r"((r)[1]) : "r"(a))
#define MMA(c, a, b0, b1) \
    asm volatile("mma.sync.aligned.m16n8k16.row.col.f32.bf16.bf16.f32 " \
        "{%0,%1,%2,%3},{%4,%5,%6,%7},{%8,%9},{%0,%1,%2,%3};" \
        : "+f"((c)[0]), "+f"((c)[1]), "+f"((c)[2]), "+f"((c)[3]) \
        : "r"((a)[0]), "r"((a)[1]), "r"((a)[2]), "r"((a)[3]), "r"(b0), "r"(b1))
#define CP_COMMIT() asm volatile("cp.async.commit_group;" ::: "memory")
#define CP_WAIT0()  asm volatile("cp.async.wait_group 0;" ::: "memory")
#define CP_WAIT1()  asm volatile("cp.async.wait_group 1;" ::: "memory")

__device__ __forceinline__ uint32_t pack_bf2(float a, float b) {
    __nv_bfloat162 h = __floats2bfloat162_rn(a, b);
    return *reinterpret_cast<uint32_t*>(&h);
}
__device__ __forceinline__ void split_pair(float a, float b, uint32_t& hi, uint32_t& lo) {
    __nv_bfloat16 ha = __float2bfloat16(a), hb = __float2bfloat16(b);
    float ra = a - __bfloat162float(ha), rb = b - __bfloat162float(hb);
    hi = pack_bf2(__bfloat162float(ha), __bfloat162float(hb));
    lo = pack_bf2(ra, rb);
}
__device__ __forceinline__ float silu(float v) {
    return v * (1.0f / (1.0f + __expf(-v)));
}

// copy one W k-panel (kp: k = kp*32..+32) hi+lo into smem buffer via cp.async
__device__ __forceinline__ void copy_panel(uint32_t dstbase,
                                           const __nv_bfloat16* __restrict__ Whi,
                                           const __nv_bfloat16* __restrict__ Wlo,
                                           int kp, int tid)
{
    #pragma unroll
    for (int i = 0; i < 4; ++i) {
        int id = i * 512 + tid;            // 0..2047
        int half = id >> 10;               // 0=hi 1=lo
        int rem  = id & 1023;
        int n = rem >> 2, c = rem & 3;     // row, 16B chunk
        const __nv_bfloat16* src = (half ? Wlo : Whi) + n * 256 + kp * 32 + c * 8;
        uint32_t dst = dstbase + half * WHALF + n * WRS + c * 16;
        asm volatile("cp.async.cg.shared.global [%0], [%1], 16;" :: "r"(dst), "l"(src) : "memory");
    }
}

// GEMM mainloop: acc[i][q] covers m = mw*64+i*16.., n = q*64 + nw*8..
__device__ __forceinline__ void gemm_main(uint32_t sb,
                                          const __nv_bfloat16* __restrict__ Whi,
                                          const __nv_bfloat16* __restrict__ Wlo,
                                          float acc[4][4][4],
                                          int tid, int l, int mw, int nw)
{
    const uint32_t aHiBase = sb + SM_A_HI
        + (uint32_t)(mw * 64 + ((l >> 3) & 1) * 8 + (l & 7)) * ARS
        + ((l >> 4) & 1) * 16;
    const uint32_t aLoBase = aHiBase + (SM_A_LO - SM_A_HI);
    // B x2: lanes 0-15 address 8 n-rows twice (k0 / k8 halves)
    const int ll = l & 15;
    const uint32_t bOff =
        (uint32_t)(nw * 8 + (ll & 7)) * WRS + ((ll >> 3) & 1) * 16;

    #pragma unroll 1
    for (int p = 0; p < 8; ++p) {
        if (p < 7) {
            copy_panel(sb + SM_W + ((p + 1) & 1) * WBUF, Whi, Wlo, p + 1, tid);
            CP_COMMIT();
            CP_WAIT1();
        } else {
            CP_WAIT0();
        }
        __syncthreads();
        const uint32_t wb = sb + SM_W + (p & 1) * WBUF;

        #pragma unroll
        for (int ks = 0; ks < 2; ++ks) {
            const int kg = p * 2 + ks;
            uint32_t Bh[4][2], Bl[4][2], Ah[4][4];
            #pragma unroll
            for (int q = 0; q < 4; ++q) {
                uint32_t ba = wb + bOff + (uint32_t)q * (64 * WRS) + ks * 32;
                LDX2(Bh[q], ba);
                LDX2(Bl[q], ba + WHALF);
            }
            #pragma unroll
            for (int i = 0; i < 4; ++i)
                LDX4(Ah[i], aHiBase + (uint32_t)i * (16 * ARS) + kg * 32);
            // pass 1: hi*hi
            #pragma unroll
            for (int i = 0; i < 4; ++i)
                #pragma unroll
                for (int q = 0; q < 4; ++q)
                    MMA(acc[i][q], Ah[i], Bh[q][0], Bh[q][1]);
            // pass 2: hi*lo(W)
            #pragma unroll
            for (int i = 0; i < 4; ++i)
                #pragma unroll
                for (int q = 0; q < 4; ++q)
                    MMA(acc[i][q], Ah[i], Bl[q][0], Bl[q][1]);
            // pass 3: lo(A)*hi
            #pragma unroll
            for (int i = 0; i < 4; ++i)
                LDX4(Ah[i], aLoBase + (uint32_t)i * (16 * ARS) + kg * 32);
            #pragma unroll
            for (int i = 0; i < 4; ++i)
                #pragma unroll
                for (int q = 0; q < 4; ++q)
                    MMA(acc[i][q], Ah[i], Bh[q][0], Bh[q][1]);
        }
        __syncthreads();
    }
}

extern "C" __global__ void __launch_bounds__(512, 1)
wavelet_mma(const float* __restrict__ x,
            const float* __restrict__ conv_b,
            const float* __restrict__ conv_out_b,
            float* __restrict__ out)
{
    extern __shared__ char sm[];
    const uint32_t sb = smem_u32(sm);
    const int tid = threadIdx.x;
    const int l  = tid & 31, wid = tid >> 5;
    const int nw = wid & 7,  mw  = wid >> 3;
    const int blk = blockIdx.x;
    const int n_img = blk >> 5, p = blk & 31;
    const size_t img_off = (size_t)n_img * C_ * HW_;
    const float* xb = x + img_off + (size_t)(4 * p) * W_;

    // prefetch GEMM1 panel 0 while we do the DWT
    copy_panel(sb + SM_W, g_Whi[0], g_Wlo[0], 0, tid);
    CP_COMMIT();

    // ---- DWT -> A hi/lo [m=128][k=256] bf16, padded rows ----
    #pragma unroll
    for (int i = 0; i < 8; ++i) {
        int e = i * 512 + tid;
        int cpair = e >> 7, m = e & 127;
        int c0 = cpair * 2, hl = m >> 6, wh = m & 63;
        const float* px = xb + (size_t)c0 * HW_ + (size_t)(2 * hl) * W_ + 2 * wh;
        float2 t0 = *(const float2*)px,         b0 = *(const float2*)(px + W_);
        float2 t1 = *(const float2*)(px + HW_), b1 = *(const float2*)(px + HW_ + W_);
        float x1 = t0.x * 0.5f, x3 = t0.y * 0.5f, x2 = b0.x * 0.5f, x4 = b0.y * 0.5f;
        float qa[4] = { x1 + x2 + x3 + x4, -x1 - x2 + x3 + x4,
                       -x1 + x2 - x3 + x4,  x1 - x2 - x3 + x4};
        x1 = t1.x * 0.5f; x3 = t1.y * 0.5f; x2 = b1.x * 0.5f; x4 = b1.y * 0.5f;
        float qb[4] = { x1 + x2 + x3 + x4, -x1 - x2 + x3 + x4,
                       -x1 + x2 - x3 + x4,  x1 - x2 - x3 + x4};
        #pragma unroll
        for (int q = 0; q < 4; ++q) {
            uint32_t hi, lo;
            split_pair(qa[q], qb[q], hi, lo);
            uint32_t off = (uint32_t)m * ARS + (uint32_t)(q * 64 + c0) * 2;
            *(uint32_t*)(sm + SM_A_HI + off) = hi;
            *(uint32_t*)(sm + SM_A_LO + off) = lo;
        }
    }

    float acc[4][4][4];
    #pragma unroll
    for (int i = 0; i < 4; ++i)
        #pragma unroll
        for (int q = 0; q < 4; ++q)
            #pragma unroll
            for (int r = 0; r < 4; ++r) acc[i][q][r] = 0.f;

    // ---- GEMM1 ----
    gemm_main(sb, g_Whi[0], g_Wlo[0], acc, tid, l, mw, nw);

    // prefetch GEMM2 panel 0 (buf0 free after gemm_main's final sync)
    copy_panel(sb + SM_W, g_Whi[1], g_Wlo[1], 0, tid);
    CP_COMMIT();

    // ---- epilogue 1: bias + SiLU -> A hi/lo (feat) ----
    {
        float bv[4][2];
        #pragma unroll
        for (int q = 0; q < 4; ++q)
            #pragma unroll
            for (int cp = 0; cp < 2; ++cp)
                bv[q][cp] = __ldg(conv_b + q * 64 + nw * 8 + (l & 3) * 2 + cp);
        #pragma unroll
        for (int i = 0; i < 4; ++i)
            #pragma unroll
            for (int rh = 0; rh < 2; ++rh) {
                int m = mw * 64 + i * 16 + rh * 8 + (l >> 2);
                #pragma unroll
                for (int q = 0; q < 4; ++q) {
                    float v0 = silu(acc[i][q][rh * 2 + 0] + bv[q][0]);
                    float v1 = silu(acc[i][q][rh * 2 + 1] + bv[q][1]);
                    uint32_t hi, lo;
                    split_pair(v0, v1, hi, lo);
                    int col = q * 64 + nw * 8 + (l & 3) * 2;
                    uint32_t off = (uint32_t)m * ARS + (uint32_t)col * 2;
                    *(uint32_t*)(sm + SM_A_HI + off) = hi;
                    *(uint32_t*)(sm + SM_A_LO + off) = lo;
                }
            }
    }
    #pragma unroll
    for (int i = 0; i < 4; ++i)
        #pragma unroll
        for (int q = 0; q < 4; ++q)
            #pragma unroll
            for (int r = 0; r < 4; ++r) acc[i][q][r] = 0.f;

    // ---- GEMM2 ---- (gemm_main's first __syncthreads orders epilogue writes)
    gemm_main(sb, g_Whi[1], g_Wlo[1], acc, tid, l, mw, nw);

    // ---- epilogue 2: bias + IDWT + store ----
    {
        float bv[4][2];
        #pragma unroll
        for (int q = 0; q < 4; ++q)
            #pragma unroll
            for (int cp = 0; cp < 2; ++cp)
                bv[q][cp] = __ldg(conv_out_b + q * 64 + nw * 8 + (l & 3) * 2 + cp);
        const int r0 = 4 * p + 2 * mw;     // hl == mw
        #pragma unroll
        for (int i = 0; i < 4; ++i)
            #pragma unroll
            for (int rh = 0; rh < 2; ++rh) {
                int m = mw * 64 + i * 16 + rh * 8 + (l >> 2);
                int wh = m & 63;
                #pragma unroll
                for (int cp = 0; cp < 2; ++cp) {
                    int co = nw * 8 + (l & 3) * 2 + cp;
                    float y1 = (acc[i][0][rh * 2 + cp] + bv[0][cp]) * 0.5f;
                    float y2 = (acc[i][1][rh * 2 + cp] + bv[1][cp]) * 0.5f;
                    float y3 = (acc[i][2][rh * 2 + cp] + bv[2][cp]) * 0.5f;
                    float y4 = (acc[i][3][rh * 2 + cp] + bv[3][cp]) * 0.5f;
                    float va = y1 - y2 - y3 + y4;
                    float vb = y1 - y2 + y3 - y4;
                    float vc = y1 + y2 - y3 - y4;
                    float vd = y1 + y2 + y3 + y4;
                    float* po = out + img_off + (size_t)co * HW_
                              + (size_t)r0 * W_ + 2 * wh;
                    *(float2*)po        = make_float2(va, vc);
                    *(float2*)(po + W_) = make_float2(vb, vd);
                }
            }
    }
}

extern "C" void kernel_launch(void* const* d_in, const int* in_sizes, int n_in,
                              void* d_out, int out_size)
{
    const float* x          = (const float*)d_in[0];
    const float* conv_w     = (const float*)d_in[1];
    const float* conv_b     = (const float*)d_in[2];
    const float* conv_out_w = (const float*)d_in[3];
    const float* conv_out_b = (const float*)d_in[4];
    float* out = (float*)d_out;

    prep_split<<<256, 256>>>(conv_w, conv_out_w);

    cudaFuncSetAttribute(wavelet_mma,
                         cudaFuncAttributeMaxDynamicSharedMemorySize, SM_TOTAL);
    wavelet_mma<<<512, 512, SM_TOTAL>>>(x, conv_b, conv_out_b, out);
}